// round 7
// baseline (speedup 1.0000x reference)
#include <cuda_runtime.h>
#include <math.h>
#include <stdint.h>

#define BB 4
#define TT 2048
#define HH 1024
#define NH 16
#define HD 64
#define H3 3072

// Scratch (allocation-free rule: __device__ globals)
__device__ float g_qkv[(size_t)BB * TT * H3];   // (B,T,3H)
__device__ float g_att[(size_t)BB * TT * HH];   // (B,T,H), tf32-rounded
__device__ float g_xr [(size_t)BB * TT * HH];   // input, tf32-rounded
__device__ float g_wqT[(size_t)H3 * HH];        // w_qkv^T (3H,H), tf32-rounded
__device__ float g_woT[(size_t)HH * HH];        // w_out^T (H,H), tf32-rounded
__device__ int   g_len[BB];

// ---------------------------------------------------------------------------
// helpers
// ---------------------------------------------------------------------------
__device__ __forceinline__ unsigned f2tf32(float f) {
    unsigned u;
    asm("cvt.rna.tf32.f32 %0, %1;" : "=r"(u) : "f"(f));
    return u;
}

__device__ __forceinline__ void mma_tf32(
    float* d, const unsigned* a, const unsigned* b)
{
    asm volatile(
        "mma.sync.aligned.m16n8k8.row.col.f32.tf32.tf32.f32 "
        "{%0,%1,%2,%3}, {%4,%5,%6,%7}, {%8,%9}, {%0,%1,%2,%3};\n"
        : "+f"(d[0]), "+f"(d[1]), "+f"(d[2]), "+f"(d[3])
        : "r"(a[0]), "r"(a[1]), "r"(a[2]), "r"(a[3]),
          "r"(b[0]), "r"(b[1]));
}

__device__ __forceinline__ uint32_t smem_u32(const void* p) {
    uint32_t a;
    asm("{ .reg .u64 t; cvta.to.shared.u64 t, %1; cvt.u32.u64 %0, t; }"
        : "=r"(a) : "l"(p));
    return a;
}

#define CP16(dst, src) \
    asm volatile("cp.async.ca.shared.global [%0], [%1], 16;" \
                 :: "r"(dst), "l"(src) : "memory")
#define CPCOMMIT() asm volatile("cp.async.commit_group;" ::: "memory")

#define LDSM4(r0, r1, r2, r3, addr) \
    asm volatile("ldmatrix.sync.aligned.m8n8.x4.shared.b16 {%0,%1,%2,%3}, [%4];" \
                 : "=r"(r0), "=r"(r1), "=r"(r2), "=r"(r3) : "r"(addr))

// ---------------------------------------------------------------------------
// Per-batch valid-prefix length; mask dtype sniffed from first 4 bytes.
// ---------------------------------------------------------------------------
__global__ void len_kernel(const unsigned char* __restrict__ mask) {
    __shared__ int sred[256];
    const unsigned int w0 = *(const unsigned int*)mask;
    const int b = blockIdx.x;
    int cnt = 0;
    if (w0 == 0x01010101u) {
        for (int t = threadIdx.x; t < TT; t += 256)
            cnt += (mask[(size_t)b * TT + t] != 0) ? 1 : 0;
    } else if (w0 == 0x3F800000u) {
        const float* m = (const float*)mask;
        for (int t = threadIdx.x; t < TT; t += 256)
            cnt += (m[(size_t)b * TT + t] != 0.f) ? 1 : 0;
    } else {
        const int* m = (const int*)mask;
        for (int t = threadIdx.x; t < TT; t += 256)
            cnt += (m[(size_t)b * TT + t] != 0) ? 1 : 0;
    }
    sred[threadIdx.x] = cnt;
    __syncthreads();
    for (int s = 128; s > 0; s >>= 1) {
        if (threadIdx.x < s) sred[threadIdx.x] += sred[threadIdx.x + s];
        __syncthreads();
    }
    if (threadIdx.x == 0) g_len[b] = sred[0];
}

// ---------------------------------------------------------------------------
// Round fp32 array to tf32 (rna) in a scratch copy.
// ---------------------------------------------------------------------------
__global__ void cvt_pre(const float4* __restrict__ in, float4* __restrict__ out,
                        int n4)
{
    for (int i = blockIdx.x * blockDim.x + threadIdx.x; i < n4;
         i += gridDim.x * blockDim.x) {
        float4 v = in[i];
        float4 r = { __uint_as_float(f2tf32(v.x)), __uint_as_float(f2tf32(v.y)),
                     __uint_as_float(f2tf32(v.z)), __uint_as_float(f2tf32(v.w)) };
        out[i] = r;
    }
}

// ---------------------------------------------------------------------------
// Weight transpose + tf32 round: D(C,R) = round(S(R,C)^T)
// ---------------------------------------------------------------------------
__global__ void transpose_w(const float* __restrict__ S, float* __restrict__ D,
                            int R, int C)
{
    __shared__ float t[32][33];
    const int x = blockIdx.x * 32 + threadIdx.x;
    const int y0 = blockIdx.y * 32;
    #pragma unroll
    for (int i = threadIdx.y; i < 32; i += 8)
        t[i][threadIdx.x] = S[(size_t)(y0 + i) * C + x];
    __syncthreads();
    const int xo = y0 + threadIdx.x;
    const int yo0 = blockIdx.x * 32;
    #pragma unroll
    for (int i = threadIdx.y; i < 32; i += 8)
        D[(size_t)(yo0 + i) * R + xo] =
            __uint_as_float(f2tf32(t[threadIdx.x][i]));
}

// ---------------------------------------------------------------------------
// tf32 HMMA GEMM with ldmatrix fragments + cp.async staging.
// C(M,N) = A(M,K) @ Bt(N,K)^T + bias(N).  A, Bt pre-rounded to tf32.
// CTA 128x128, K-chunk 16, 8 warps (warpM 0..1 x warpN 0..3), warp tile 64x32.
// Smem tiles: rows of 16 floats (64B) -> LDSM conflict-free, no swizzle.
// ---------------------------------------------------------------------------
__global__ __launch_bounds__(256) void tgemm_ldsm(
    const float* __restrict__ A, const float* __restrict__ Bt,
    const float* __restrict__ bias, float* __restrict__ C,
    int M, int N, int K)
{
    __shared__ float As[2][128][16];
    __shared__ float Bs[2][128][16];

    const int tid   = threadIdx.x;
    const int warp  = tid >> 5;
    const int lane  = tid & 31;
    const int g     = lane >> 2;
    const int t     = lane & 3;
    const int warpM = warp & 1;
    const int warpN = warp >> 1;
    const int brow  = blockIdx.y * 128;
    const int bcol  = blockIdx.x * 128;

    // ---- loader: thread -> row tid/2, 8 floats at (tid&1)*8 ----
    const int lrow = tid >> 1;
    const int lq   = (tid & 1) * 8;
    const float* Ap = A  + (size_t)(brow + lrow) * K + lq;
    const float* Bp = Bt + (size_t)(bcol + lrow) * K + lq;
    uint32_t dA[2], dB[2];
    dA[0] = smem_u32(&As[0][lrow][lq]);
    dA[1] = smem_u32(&As[1][lrow][lq]);
    dB[0] = smem_u32(&Bs[0][lrow][lq]);
    dB[1] = smem_u32(&Bs[1][lrow][lq]);

    // ---- consumer LDSM per-lane base addresses ----
    // A tile order {a0,a1,a2,a3}: rows (lane&7)+((lane>>3)&1)*8, 16B half lane>>4
    const int arow = (lane & 7) + ((lane >> 3) & 1) * 8;
    const int acol = (lane >> 4) * 16;           // byte
    // B tile order {b0,b1,b0',b1'}: rows (lane&7)+(lane>>4)*8, half (lane>>3)&1
    const int brow_i = (lane & 7) + (lane >> 4) * 8;
    const int bcol_i = ((lane >> 3) & 1) * 16;   // byte
    uint32_t aAddr[2], bAddr[2];
    aAddr[0] = smem_u32(&As[0][warpM * 64 + arow][0]) + acol;
    aAddr[1] = smem_u32(&As[1][warpM * 64 + arow][0]) + acol;
    bAddr[0] = smem_u32(&Bs[0][warpN * 32 + brow_i][0]) + bcol_i;
    bAddr[1] = smem_u32(&Bs[1][warpN * 32 + brow_i][0]) + bcol_i;

    float acc[4][4][4];
    #pragma unroll
    for (int i = 0; i < 4; i++)
        #pragma unroll
        for (int j = 0; j < 4; j++)
            #pragma unroll
            for (int q = 0; q < 4; q++) acc[i][j][q] = 0.f;

    const int nch = K >> 4;

    // prologue: stage chunk 0
    CP16(dA[0],      Ap);
    CP16(dA[0] + 16, Ap + 4);
    CP16(dB[0],      Bp);
    CP16(dB[0] + 16, Bp + 4);
    CPCOMMIT();

    for (int kc = 0; kc < nch; kc++) {
        const int st = kc & 1;

        if (kc + 1 < nch) {
            const int sn = st ^ 1;
            const float* Ap2 = Ap + (kc + 1) * 16;
            const float* Bp2 = Bp + (kc + 1) * 16;
            CP16(dA[sn],      Ap2);
            CP16(dA[sn] + 16, Ap2 + 4);
            CP16(dB[sn],      Bp2);
            CP16(dB[sn] + 16, Bp2 + 4);
            CPCOMMIT();
            asm volatile("cp.async.wait_group 1;" ::: "memory");
        } else {
            asm volatile("cp.async.wait_group 0;" ::: "memory");
        }
        __syncthreads();

        #pragma unroll
        for (int ks = 0; ks < 2; ks++) {
            const int kb = ks * 32;   // byte offset of k8 sub-chunk
            unsigned af[4][4];
            #pragma unroll
            for (int mt = 0; mt < 4; mt++)
                LDSM4(af[mt][0], af[mt][1], af[mt][2], af[mt][3],
                      aAddr[st] + mt * 1024 + kb);
            unsigned bf[4][2];
            #pragma unroll
            for (int np = 0; np < 2; np++) {
                unsigned r0, r1, r2, r3;
                LDSM4(r0, r1, r2, r3, bAddr[st] + np * 1024 + kb);
                bf[np * 2][0] = r0;  bf[np * 2][1] = r1;
                bf[np * 2 + 1][0] = r2;  bf[np * 2 + 1][1] = r3;
            }
            #pragma unroll
            for (int mt = 0; mt < 4; mt++)
                #pragma unroll
                for (int nt = 0; nt < 4; nt++)
                    mma_tf32(acc[mt][nt], af[mt], bf[nt]);
        }
        __syncthreads();
    }

    // epilogue: bias + store
    #pragma unroll
    for (int mt = 0; mt < 4; mt++) {
        const int r0 = brow + warpM * 64 + mt * 16 + g;
        #pragma unroll
        for (int nt = 0; nt < 4; nt++) {
            const int c = bcol + warpN * 32 + nt * 8 + 2 * t;
            const float bv0 = bias[c], bv1 = bias[c + 1];
            float2 v0 = {acc[mt][nt][0] + bv0, acc[mt][nt][1] + bv1};
            float2 v1 = {acc[mt][nt][2] + bv0, acc[mt][nt][3] + bv1};
            *(float2*)&C[(size_t)r0 * N + c]       = v0;
            *(float2*)&C[(size_t)(r0 + 8) * N + c] = v1;
        }
    }
}

// ---------------------------------------------------------------------------
// Flash attention with tf32 MMA; K/V tiles register-prefetched one kt ahead.
// Epilogue stores tf32-rounded values (consumed only by the proj GEMM).
// ---------------------------------------------------------------------------
__global__ __launch_bounds__(256) void attn_mma(
    const float* __restrict__ qkv, float* __restrict__ att)
{
    extern __shared__ unsigned smu[];
    unsigned* Qs = smu;
    unsigned* Ks = smu + 64 * 68;
    unsigned* Vs = smu + 2 * 64 * 68;
    float*    Ps = (float*)(smu + 3 * 64 * 68);
    float*    m_s = Ps + 64 * 68;
    float*    l_s = m_s + 64;
    float*    a_s = l_s + 64;

    const int tid  = threadIdx.x;
    const int warp = tid >> 5;
    const int lane = tid & 31;
    const int g = lane >> 2;
    const int t = lane & 3;
    const int wm = warp >> 1;
    const int wn = warp & 1;
    const int qt = blockIdx.x;
    const int b  = blockIdx.y >> 4;
    const int h  = blockIdx.y & 15;
    const int len = g_len[b];

    const float* qb = qkv + (size_t)b * TT * H3 + h * HD;
    const float* kb = qb + HH;
    const float* vb = qb + 2 * HH;

    const int rr = tid >> 4;
    const int d0 = (tid & 15) * 4;

    #pragma unroll
    for (int it = 0; it < 4; it++) {
        const int r = rr + it * 16;
        float4 q4 = *(const float4*)(qb + (size_t)(qt * 64 + r) * H3 + d0);
        Qs[r * 68 + d0 + 0] = f2tf32(q4.x);
        Qs[r * 68 + d0 + 1] = f2tf32(q4.y);
        Qs[r * 68 + d0 + 2] = f2tf32(q4.z);
        Qs[r * 68 + d0 + 3] = f2tf32(q4.w);
    }
    if (tid < 64) { m_s[tid] = -1e30f; l_s[tid] = 0.f; }

    float o[4][4];
    #pragma unroll
    for (int nt = 0; nt < 4; nt++)
        #pragma unroll
        for (int q = 0; q < 4; q++) o[nt][q] = 0.f;

    const int kt_max = min(qt, (len - 1) >> 6);

    float4 kreg[4], vreg[4];
    #pragma unroll
    for (int it = 0; it < 4; it++) {
        const int c = rr + it * 16;
        kreg[it] = *(const float4*)(kb + (size_t)c * H3 + d0);
        vreg[it] = *(const float4*)(vb + (size_t)c * H3 + d0);
    }
    __syncthreads();

    for (int kt = 0; kt <= kt_max; kt++) {
        #pragma unroll
        for (int it = 0; it < 4; it++) {
            const int c = rr + it * 16;
            Ks[c * 68 + d0 + 0] = f2tf32(kreg[it].x);
            Ks[c * 68 + d0 + 1] = f2tf32(kreg[it].y);
            Ks[c * 68 + d0 + 2] = f2tf32(kreg[it].z);
            Ks[c * 68 + d0 + 3] = f2tf32(kreg[it].w);
            Vs[c * 68 + d0 + 0] = f2tf32(vreg[it].x);
            Vs[c * 68 + d0 + 1] = f2tf32(vreg[it].y);
            Vs[c * 68 + d0 + 2] = f2tf32(vreg[it].z);
            Vs[c * 68 + d0 + 3] = f2tf32(vreg[it].w);
        }
        __syncthreads();

        if (kt < kt_max) {
            #pragma unroll
            for (int it = 0; it < 4; it++) {
                const int c = (kt + 1) * 64 + rr + it * 16;
                kreg[it] = *(const float4*)(kb + (size_t)c * H3 + d0);
                vreg[it] = *(const float4*)(vb + (size_t)c * H3 + d0);
            }
        }

        float s[4][4];
        #pragma unroll
        for (int nt = 0; nt < 4; nt++)
            #pragma unroll
            for (int q = 0; q < 4; q++) s[nt][q] = 0.f;

        #pragma unroll
        for (int k0 = 0; k0 < 64; k0 += 8) {
            unsigned af[4];
            const int r0 = wm * 16;
            af[0] = Qs[(r0 + g) * 68 + k0 + t];
            af[1] = Qs[(r0 + g + 8) * 68 + k0 + t];
            af[2] = Qs[(r0 + g) * 68 + k0 + t + 4];
            af[3] = Qs[(r0 + g + 8) * 68 + k0 + t + 4];
            #pragma unroll
            for (int nt = 0; nt < 4; nt++) {
                const int c = wn * 32 + nt * 8 + g;
                unsigned bf[2] = { Ks[c * 68 + k0 + t], Ks[c * 68 + k0 + t + 4] };
                mma_tf32(s[nt], af, bf);
            }
        }

        {
            const int r0 = wm * 16 + g;
            const int q0 = qt * 64;
            #pragma unroll
            for (int nt = 0; nt < 4; nt++) {
                const int c0 = wn * 32 + nt * 8 + 2 * t;
                const int kc = kt * 64 + c0;
                Ps[r0 * 68 + c0] =
                    (kc <= q0 + r0 && kc < len) ? s[nt][0] * 0.125f : -1e30f;
                Ps[r0 * 68 + c0 + 1] =
                    (kc + 1 <= q0 + r0 && kc + 1 < len) ? s[nt][1] * 0.125f : -1e30f;
                Ps[(r0 + 8) * 68 + c0] =
                    (kc <= q0 + r0 + 8 && kc < len) ? s[nt][2] * 0.125f : -1e30f;
                Ps[(r0 + 8) * 68 + c0 + 1] =
                    (kc + 1 <= q0 + r0 + 8 && kc + 1 < len) ? s[nt][3] * 0.125f : -1e30f;
            }
        }
        __syncthreads();

        {
            const int r = tid >> 2, qq = tid & 3;
            float* prow = Ps + r * 68 + qq * 16;
            float mx = -1e30f;
            #pragma unroll
            for (int c = 0; c < 16; c++) mx = fmaxf(mx, prow[c]);
            mx = fmaxf(mx, __shfl_xor_sync(0xffffffffu, mx, 1));
            mx = fmaxf(mx, __shfl_xor_sync(0xffffffffu, mx, 2));
            const float mo = m_s[r];
            const float mn = fmaxf(mo, mx);
            float sum = 0.f;
            #pragma unroll
            for (int c = 0; c < 16; c++) {
                float e = __expf(prow[c] - mn);
                prow[c] = __uint_as_float(f2tf32(e));
                sum += e;
            }
            sum += __shfl_xor_sync(0xffffffffu, sum, 1);
            sum += __shfl_xor_sync(0xffffffffu, sum, 2);
            if (qq == 0) {
                float a = __expf(mo - mn);
                a_s[r] = a;
                l_s[r] = l_s[r] * a + sum;
                m_s[r] = mn;
            }
        }
        __syncthreads();

        {
            const float a0 = a_s[wm * 16 + g];
            const float a1 = a_s[wm * 16 + g + 8];
            #pragma unroll
            for (int nt = 0; nt < 4; nt++) {
                o[nt][0] *= a0; o[nt][1] *= a0;
                o[nt][2] *= a1; o[nt][3] *= a1;
            }
        }

        {
            const unsigned* Pu = (const unsigned*)Ps;
            #pragma unroll
            for (int k0 = 0; k0 < 64; k0 += 8) {
                unsigned af[4];
                const int r0 = wm * 16;
                af[0] = Pu[(r0 + g) * 68 + k0 + t];
                af[1] = Pu[(r0 + g + 8) * 68 + k0 + t];
                af[2] = Pu[(r0 + g) * 68 + k0 + t + 4];
                af[3] = Pu[(r0 + g + 8) * 68 + k0 + t + 4];
                #pragma unroll
                for (int nt = 0; nt < 4; nt++) {
                    const int c = wn * 32 + nt * 8 + g;
                    unsigned bf[2] = { Vs[(k0 + t) * 68 + c],
                                       Vs[(k0 + t + 4) * 68 + c] };
                    mma_tf32(o[nt], af, bf);
                }
            }
        }
        __syncthreads();
    }

    {
        const int r0 = wm * 16 + g;
        const float inv0 = 1.f / l_s[r0];
        const float inv1 = 1.f / l_s[r0 + 8];
        float* ob = att + (size_t)b * TT * HH + (size_t)(qt * 64) * HH + h * HD;
        #pragma unroll
        for (int nt = 0; nt < 4; nt++) {
            const int c = wn * 32 + nt * 8 + 2 * t;
            float2 v0 = { __uint_as_float(f2tf32(o[nt][0] * inv0)),
                          __uint_as_float(f2tf32(o[nt][1] * inv0)) };
            float2 v1 = { __uint_as_float(f2tf32(o[nt][2] * inv1)),
                          __uint_as_float(f2tf32(o[nt][3] * inv1)) };
            *(float2*)&ob[(size_t)r0 * HH + c]       = v0;
            *(float2*)&ob[(size_t)(r0 + 8) * HH + c] = v1;
        }
    }
}

// ---------------------------------------------------------------------------

static const int ATTN_SMEM = (4 * 64 * 68 + 3 * 64) * 4;  // 70400 B

extern "C" void kernel_launch(void* const* d_in, const int* in_sizes, int n_in,
                              void* d_out, int out_size)
{
    const float*         inp   = (const float*)d_in[0];
    const unsigned char* mask  = (const unsigned char*)d_in[1];
    const float*         w_qkv = (const float*)d_in[2];
    const float*         b_qkv = (const float*)d_in[3];
    const float*         w_out = (const float*)d_in[4];
    const float*         b_out = (const float*)d_in[5];
    float*               out   = (float*)d_out;

    float *qkv_p, *att_p, *xr_p, *wqT_p, *woT_p;
    cudaGetSymbolAddress((void**)&qkv_p, g_qkv);
    cudaGetSymbolAddress((void**)&att_p, g_att);
    cudaGetSymbolAddress((void**)&xr_p,  g_xr);
    cudaGetSymbolAddress((void**)&wqT_p, g_wqT);
    cudaGetSymbolAddress((void**)&woT_p, g_woT);

    cudaFuncSetAttribute(attn_mma,
                         cudaFuncAttributeMaxDynamicSharedMemorySize, ATTN_SMEM);

    len_kernel<<<BB, 256>>>(mask);
    cvt_pre<<<512, 256>>>((const float4*)inp, (float4*)xr_p,
                          (BB * TT * HH) / 4);
    transpose_w<<<dim3(H3 / 32, HH / 32), dim3(32, 8)>>>(w_qkv, wqT_p, HH, H3);
    transpose_w<<<dim3(HH / 32, HH / 32), dim3(32, 8)>>>(w_out, woT_p, HH, HH);

    tgemm_ldsm<<<dim3(H3 / 128, (BB * TT) / 128), 256>>>(
        xr_p, wqT_p, b_qkv, qkv_p, BB * TT, H3, HH);
    attn_mma<<<dim3(TT / 64, BB * NH), 256, ATTN_SMEM>>>(qkv_p, att_p);
    tgemm_ldsm<<<dim3(HH / 128, (BB * TT) / 128), 256>>>(
        att_p, woT_p, b_out, out, BB * TT, HH, HH);
}

// round 8
// speedup vs baseline: 1.5161x; 1.5161x over previous
#include <cuda_runtime.h>
#include <math.h>
#include <stdint.h>

#define BB 4
#define TT 2048
#define HH 1024
#define NH 16
#define HD 64
#define H3 3072

// Scratch (allocation-free rule: __device__ globals)
__device__ float g_qkv[(size_t)BB * TT * H3];   // (B,T,3H)
__device__ float g_att[(size_t)BB * TT * HH];   // (B,T,H), tf32-rounded
__device__ float g_xr [(size_t)BB * TT * HH];   // input, tf32-rounded
__device__ float g_wqT[(size_t)H3 * HH];        // w_qkv^T (3H,H), tf32-rounded
__device__ float g_woT[(size_t)HH * HH];        // w_out^T (H,H), tf32-rounded
__device__ int   g_len[BB];

// ---------------------------------------------------------------------------
// helpers
// ---------------------------------------------------------------------------
__device__ __forceinline__ unsigned f2tf32(float f) {
    unsigned u;
    asm("cvt.rna.tf32.f32 %0, %1;" : "=r"(u) : "f"(f));
    return u;
}

__device__ __forceinline__ void mma_tf32(
    float* d, const unsigned* a, const unsigned* b)
{
    asm volatile(
        "mma.sync.aligned.m16n8k8.row.col.f32.tf32.tf32.f32 "
        "{%0,%1,%2,%3}, {%4,%5,%6,%7}, {%8,%9}, {%0,%1,%2,%3};\n"
        : "+f"(d[0]), "+f"(d[1]), "+f"(d[2]), "+f"(d[3])
        : "r"(a[0]), "r"(a[1]), "r"(a[2]), "r"(a[3]),
          "r"(b[0]), "r"(b[1]));
}

__device__ __forceinline__ uint32_t smem_u32(const void* p) {
    uint32_t a;
    asm("{ .reg .u64 t; cvta.to.shared.u64 t, %1; cvt.u32.u64 %0, t; }"
        : "=r"(a) : "l"(p));
    return a;
}

#define CP16(dst, src) \
    asm volatile("cp.async.ca.shared.global [%0], [%1], 16;" \
                 :: "r"(dst), "l"(src) : "memory")
#define CPCOMMIT() asm volatile("cp.async.commit_group;" ::: "memory")

#define LDSM4(r0, r1, r2, r3, addr) \
    asm volatile("ldmatrix.sync.aligned.m8n8.x4.shared.b16 {%0,%1,%2,%3}, [%4];" \
                 : "=r"(r0), "=r"(r1), "=r"(r2), "=r"(r3) : "r"(addr))

// SW128 swizzle on 16B granules within a 128B row
#define SWR(row, byteoff) (((row) * 128 + (byteoff)) ^ (((row) & 7) << 4))

// ---------------------------------------------------------------------------
// Per-batch valid-prefix length; mask dtype sniffed from first 4 bytes.
// ---------------------------------------------------------------------------
__global__ void len_kernel(const unsigned char* __restrict__ mask) {
    __shared__ int sred[256];
    const unsigned int w0 = *(const unsigned int*)mask;
    const int b = blockIdx.x;
    int cnt = 0;
    if (w0 == 0x01010101u) {
        for (int t = threadIdx.x; t < TT; t += 256)
            cnt += (mask[(size_t)b * TT + t] != 0) ? 1 : 0;
    } else if (w0 == 0x3F800000u) {
        const float* m = (const float*)mask;
        for (int t = threadIdx.x; t < TT; t += 256)
            cnt += (m[(size_t)b * TT + t] != 0.f) ? 1 : 0;
    } else {
        const int* m = (const int*)mask;
        for (int t = threadIdx.x; t < TT; t += 256)
            cnt += (m[(size_t)b * TT + t] != 0) ? 1 : 0;
    }
    sred[threadIdx.x] = cnt;
    __syncthreads();
    for (int s = 128; s > 0; s >>= 1) {
        if (threadIdx.x < s) sred[threadIdx.x] += sred[threadIdx.x + s];
        __syncthreads();
    }
    if (threadIdx.x == 0) g_len[b] = sred[0];
}

// ---------------------------------------------------------------------------
// Round fp32 array to tf32 (rna) in a scratch copy.
// ---------------------------------------------------------------------------
__global__ void cvt_pre(const float4* __restrict__ in, float4* __restrict__ out,
                        int n4)
{
    for (int i = blockIdx.x * blockDim.x + threadIdx.x; i < n4;
         i += gridDim.x * blockDim.x) {
        float4 v = in[i];
        float4 r = { __uint_as_float(f2tf32(v.x)), __uint_as_float(f2tf32(v.y)),
                     __uint_as_float(f2tf32(v.z)), __uint_as_float(f2tf32(v.w)) };
        out[i] = r;
    }
}

// ---------------------------------------------------------------------------
// Weight transpose + tf32 round: D(C,R) = round(S(R,C)^T)
// ---------------------------------------------------------------------------
__global__ void transpose_w(const float* __restrict__ S, float* __restrict__ D,
                            int R, int C)
{
    __shared__ float t[32][33];
    const int x = blockIdx.x * 32 + threadIdx.x;
    const int y0 = blockIdx.y * 32;
    #pragma unroll
    for (int i = threadIdx.y; i < 32; i += 8)
        t[i][threadIdx.x] = S[(size_t)(y0 + i) * C + x];
    __syncthreads();
    const int xo = y0 + threadIdx.x;
    const int yo0 = blockIdx.x * 32;
    #pragma unroll
    for (int i = threadIdx.y; i < 32; i += 8)
        D[(size_t)(yo0 + i) * R + xo] =
            __uint_as_float(f2tf32(t[threadIdx.x][i]));
}

// ---------------------------------------------------------------------------
// tf32 HMMA GEMM: cp.async staging + SW128-swizzled 128B rows + ldmatrix.
// C(M,N) = A(M,K) @ Bt(N,K)^T + bias(N).  A, Bt pre-rounded to tf32.
// CTA 128x128, K-chunk 32 (4 x k8), 8 warps (warpM 2 x warpN 4), 64x32/warp.
// Smem: per stage A[128][32]f, B[128][32]f; LDSM conflict-free via swizzle.
// ---------------------------------------------------------------------------
#define TG_STAGE 16384
#define TG_SMEM  (4 * TG_STAGE)   // A0 A1 B0 B1

__global__ __launch_bounds__(256) void tgemm_ldsm(
    const float* __restrict__ A, const float* __restrict__ Bt,
    const float* __restrict__ bias, float* __restrict__ C,
    int M, int N, int K)
{
    extern __shared__ char smem[];
    const uint32_t sA0 = smem_u32(smem);
    const uint32_t sB0 = sA0 + 2 * TG_STAGE;

    const int tid   = threadIdx.x;
    const int warp  = tid >> 5;
    const int lane  = tid & 31;
    const int g     = lane >> 2;
    const int t     = lane & 3;
    const int warpM = warp & 1;
    const int warpN = warp >> 1;
    const int brow  = blockIdx.y * 128;
    const int bcol  = blockIdx.x * 128;

    // ---- loader: row tid/2 (0..127), granules (tid&1)*4 + q (q=0..3) ----
    const int lrow = tid >> 1;
    const int lg   = (tid & 1) * 4;        // granule base within row
    const float* Ap = A  + (size_t)(brow + lrow) * K + lg * 4;
    const float* Bp = Bt + (size_t)(bcol + lrow) * K + lg * 4;
    uint32_t stA[2][4], stB[2][4];
    #pragma unroll
    for (int q = 0; q < 4; q++) {
        const uint32_t sw = SWR(lrow, (lg + q) * 16);
        stA[0][q] = sA0 + sw;
        stA[1][q] = sA0 + TG_STAGE + sw;
        stB[0][q] = sB0 + sw;
        stB[1][q] = sB0 + TG_STAGE + sw;
    }

    // ---- consumer LDSM lane addressing ----
    // A: matrices {rows0-7 k0-3, rows8-15 k0-3, rows0-7 k4-7, rows8-15 k4-7}
    const int arow = (lane & 7) + ((lane >> 3) & 1) * 8;
    const int acol = (lane >> 4) * 16;       // byte within k8 subchunk
    // B: matrices {n0-7 k0-3, n0-7 k4-7, n8-15 k0-3, n8-15 k4-7}
    const int brow_i = (lane & 7) + (lane >> 4) * 8;
    const int bcol_i = ((lane >> 3) & 1) * 16;

    float acc[4][4][4];
    #pragma unroll
    for (int i = 0; i < 4; i++)
        #pragma unroll
        for (int j = 0; j < 4; j++)
            #pragma unroll
            for (int q = 0; q < 4; q++) acc[i][j][q] = 0.f;

    const int nch = K >> 5;

    // prologue: stage 0 <- chunk 0
    #pragma unroll
    for (int q = 0; q < 4; q++) {
        CP16(stA[0][q], Ap + q * 4);
        CP16(stB[0][q], Bp + q * 4);
    }
    CPCOMMIT();

    for (int kc = 0; kc < nch; kc++) {
        const int st = kc & 1;

        if (kc + 1 < nch) {
            const int sn = st ^ 1;
            const float* Ap2 = Ap + (kc + 1) * 32;
            const float* Bp2 = Bp + (kc + 1) * 32;
            #pragma unroll
            for (int q = 0; q < 4; q++) {
                CP16(stA[sn][q], Ap2 + q * 4);
                CP16(stB[sn][q], Bp2 + q * 4);
            }
            CPCOMMIT();
            asm volatile("cp.async.wait_group 1;" ::: "memory");
        } else {
            asm volatile("cp.async.wait_group 0;" ::: "memory");
        }
        __syncthreads();

        const uint32_t aBase = sA0 + st * TG_STAGE;
        const uint32_t bBase = sB0 + st * TG_STAGE;

        #pragma unroll
        for (int ks = 0; ks < 4; ks++) {
            const int kb = ks * 32;   // byte offset of k8 sub-chunk
            unsigned af[4][4];
            #pragma unroll
            for (int mt = 0; mt < 4; mt++) {
                const int r = warpM * 64 + mt * 16 + arow;
                LDSM4(af[mt][0], af[mt][1], af[mt][2], af[mt][3],
                      aBase + SWR(r, kb + acol));
            }
            unsigned bf[4][2];
            #pragma unroll
            for (int np = 0; np < 2; np++) {
                const int r = warpN * 32 + np * 16 + brow_i;
                unsigned r0, r1, r2, r3;
                LDSM4(r0, r1, r2, r3, bBase + SWR(r, kb + bcol_i));
                bf[np * 2][0] = r0;      bf[np * 2][1] = r1;
                bf[np * 2 + 1][0] = r2;  bf[np * 2 + 1][1] = r3;
            }
            #pragma unroll
            for (int mt = 0; mt < 4; mt++)
                #pragma unroll
                for (int nt = 0; nt < 4; nt++)
                    mma_tf32(acc[mt][nt], af[mt], bf[nt]);
        }
        __syncthreads();
    }

    // epilogue: bias + store
    #pragma unroll
    for (int mt = 0; mt < 4; mt++) {
        const int r0 = brow + warpM * 64 + mt * 16 + g;
        #pragma unroll
        for (int nt = 0; nt < 4; nt++) {
            const int c = bcol + warpN * 32 + nt * 8 + 2 * t;
            const float bv0 = bias[c], bv1 = bias[c + 1];
            float2 v0 = {acc[mt][nt][0] + bv0, acc[mt][nt][1] + bv1};
            float2 v1 = {acc[mt][nt][2] + bv0, acc[mt][nt][3] + bv1};
            *(float2*)&C[(size_t)r0 * N + c]       = v0;
            *(float2*)&C[(size_t)(r0 + 8) * N + c] = v1;
        }
    }
}

// ---------------------------------------------------------------------------
// Flash attention with tf32 MMA; K/V tiles register-prefetched one kt ahead.
// (unchanged — proven)
// ---------------------------------------------------------------------------
__global__ __launch_bounds__(256) void attn_mma(
    const float* __restrict__ qkv, float* __restrict__ att)
{
    extern __shared__ unsigned smu[];
    unsigned* Qs = smu;
    unsigned* Ks = smu + 64 * 68;
    unsigned* Vs = smu + 2 * 64 * 68;
    float*    Ps = (float*)(smu + 3 * 64 * 68);
    float*    m_s = Ps + 64 * 68;
    float*    l_s = m_s + 64;
    float*    a_s = l_s + 64;

    const int tid  = threadIdx.x;
    const int warp = tid >> 5;
    const int lane = tid & 31;
    const int g = lane >> 2;
    const int t = lane & 3;
    const int wm = warp >> 1;
    const int wn = warp & 1;
    const int qt = blockIdx.x;
    const int b  = blockIdx.y >> 4;
    const int h  = blockIdx.y & 15;
    const int len = g_len[b];

    const float* qb = qkv + (size_t)b * TT * H3 + h * HD;
    const float* kb = qb + HH;
    const float* vb = qb + 2 * HH;

    const int rr = tid >> 4;
    const int d0 = (tid & 15) * 4;

    #pragma unroll
    for (int it = 0; it < 4; it++) {
        const int r = rr + it * 16;
        float4 q4 = *(const float4*)(qb + (size_t)(qt * 64 + r) * H3 + d0);
        Qs[r * 68 + d0 + 0] = f2tf32(q4.x);
        Qs[r * 68 + d0 + 1] = f2tf32(q4.y);
        Qs[r * 68 + d0 + 2] = f2tf32(q4.z);
        Qs[r * 68 + d0 + 3] = f2tf32(q4.w);
    }
    if (tid < 64) { m_s[tid] = -1e30f; l_s[tid] = 0.f; }

    float o[4][4];
    #pragma unroll
    for (int nt = 0; nt < 4; nt++)
        #pragma unroll
        for (int q = 0; q < 4; q++) o[nt][q] = 0.f;

    const int kt_max = min(qt, (len - 1) >> 6);

    float4 kreg[4], vreg[4];
    #pragma unroll
    for (int it = 0; it < 4; it++) {
        const int c = rr + it * 16;
        kreg[it] = *(const float4*)(kb + (size_t)c * H3 + d0);
        vreg[it] = *(const float4*)(vb + (size_t)c * H3 + d0);
    }
    __syncthreads();

    for (int kt = 0; kt <= kt_max; kt++) {
        #pragma unroll
        for (int it = 0; it < 4; it++) {
            const int c = rr + it * 16;
            Ks[c * 68 + d0 + 0] = f2tf32(kreg[it].x);
            Ks[c * 68 + d0 + 1] = f2tf32(kreg[it].y);
            Ks[c * 68 + d0 + 2] = f2tf32(kreg[it].z);
            Ks[c * 68 + d0 + 3] = f2tf32(kreg[it].w);
            Vs[c * 68 + d0 + 0] = f2tf32(vreg[it].x);
            Vs[c * 68 + d0 + 1] = f2tf32(vreg[it].y);
            Vs[c * 68 + d0 + 2] = f2tf32(vreg[it].z);
            Vs[c * 68 + d0 + 3] = f2tf32(vreg[it].w);
        }
        __syncthreads();

        if (kt < kt_max) {
            #pragma unroll
            for (int it = 0; it < 4; it++) {
                const int c = (kt + 1) * 64 + rr + it * 16;
                kreg[it] = *(const float4*)(kb + (size_t)c * H3 + d0);
                vreg[it] = *(const float4*)(vb + (size_t)c * H3 + d0);
            }
        }

        float s[4][4];
        #pragma unroll
        for (int nt = 0; nt < 4; nt++)
            #pragma unroll
            for (int q = 0; q < 4; q++) s[nt][q] = 0.f;

        #pragma unroll
        for (int k0 = 0; k0 < 64; k0 += 8) {
            unsigned af[4];
            const int r0 = wm * 16;
            af[0] = Qs[(r0 + g) * 68 + k0 + t];
            af[1] = Qs[(r0 + g + 8) * 68 + k0 + t];
            af[2] = Qs[(r0 + g) * 68 + k0 + t + 4];
            af[3] = Qs[(r0 + g + 8) * 68 + k0 + t + 4];
            #pragma unroll
            for (int nt = 0; nt < 4; nt++) {
                const int c = wn * 32 + nt * 8 + g;
                unsigned bf[2] = { Ks[c * 68 + k0 + t], Ks[c * 68 + k0 + t + 4] };
                mma_tf32(s[nt], af, bf);
            }
        }

        {
            const int r0 = wm * 16 + g;
            const int q0 = qt * 64;
            #pragma unroll
            for (int nt = 0; nt < 4; nt++) {
                const int c0 = wn * 32 + nt * 8 + 2 * t;
                const int kc = kt * 64 + c0;
                Ps[r0 * 68 + c0] =
                    (kc <= q0 + r0 && kc < len) ? s[nt][0] * 0.125f : -1e30f;
                Ps[r0 * 68 + c0 + 1] =
                    (kc + 1 <= q0 + r0 && kc + 1 < len) ? s[nt][1] * 0.125f : -1e30f;
                Ps[(r0 + 8) * 68 + c0] =
                    (kc <= q0 + r0 + 8 && kc < len) ? s[nt][2] * 0.125f : -1e30f;
                Ps[(r0 + 8) * 68 + c0 + 1] =
                    (kc + 1 <= q0 + r0 + 8 && kc + 1 < len) ? s[nt][3] * 0.125f : -1e30f;
            }
        }
        __syncthreads();

        {
            const int r = tid >> 2, qq = tid & 3;
            float* prow = Ps + r * 68 + qq * 16;
            float mx = -1e30f;
            #pragma unroll
            for (int c = 0; c < 16; c++) mx = fmaxf(mx, prow[c]);
            mx = fmaxf(mx, __shfl_xor_sync(0xffffffffu, mx, 1));
            mx = fmaxf(mx, __shfl_xor_sync(0xffffffffu, mx, 2));
            const float mo = m_s[r];
            const float mn = fmaxf(mo, mx);
            float sum = 0.f;
            #pragma unroll
            for (int c = 0; c < 16; c++) {
                float e = __expf(prow[c] - mn);
                prow[c] = __uint_as_float(f2tf32(e));
                sum += e;
            }
            sum += __shfl_xor_sync(0xffffffffu, sum, 1);
            sum += __shfl_xor_sync(0xffffffffu, sum, 2);
            if (qq == 0) {
                float a = __expf(mo - mn);
                a_s[r] = a;
                l_s[r] = l_s[r] * a + sum;
                m_s[r] = mn;
            }
        }
        __syncthreads();

        {
            const float a0 = a_s[wm * 16 + g];
            const float a1 = a_s[wm * 16 + g + 8];
            #pragma unroll
            for (int nt = 0; nt < 4; nt++) {
                o[nt][0] *= a0; o[nt][1] *= a0;
                o[nt][2] *= a1; o[nt][3] *= a1;
            }
        }

        {
            const unsigned* Pu = (const unsigned*)Ps;
            #pragma unroll
            for (int k0 = 0; k0 < 64; k0 += 8) {
                unsigned af[4];
                const int r0 = wm * 16;
                af[0] = Pu[(r0 + g) * 68 + k0 + t];
                af[1] = Pu[(r0 + g + 8) * 68 + k0 + t];
                af[2] = Pu[(r0 + g) * 68 + k0 + t + 4];
                af[3] = Pu[(r0 + g + 8) * 68 + k0 + t + 4];
                #pragma unroll
                for (int nt = 0; nt < 4; nt++) {
                    const int c = wn * 32 + nt * 8 + g;
                    unsigned bf[2] = { Vs[(k0 + t) * 68 + c],
                                       Vs[(k0 + t + 4) * 68 + c] };
                    mma_tf32(o[nt], af, bf);
                }
            }
        }
        __syncthreads();
    }

    {
        const int r0 = wm * 16 + g;
        const float inv0 = 1.f / l_s[r0];
        const float inv1 = 1.f / l_s[r0 + 8];
        float* ob = att + (size_t)b * TT * HH + (size_t)(qt * 64) * HH + h * HD;
        #pragma unroll
        for (int nt = 0; nt < 4; nt++) {
            const int c = wn * 32 + nt * 8 + 2 * t;
            float2 v0 = { __uint_as_float(f2tf32(o[nt][0] * inv0)),
                          __uint_as_float(f2tf32(o[nt][1] * inv0)) };
            float2 v1 = { __uint_as_float(f2tf32(o[nt][2] * inv1)),
                          __uint_as_float(f2tf32(o[nt][3] * inv1)) };
            *(float2*)&ob[(size_t)r0 * HH + c]       = v0;
            *(float2*)&ob[(size_t)(r0 + 8) * HH + c] = v1;
        }
    }
}

// ---------------------------------------------------------------------------

static const int ATTN_SMEM = (4 * 64 * 68 + 3 * 64) * 4;  // 70400 B

extern "C" void kernel_launch(void* const* d_in, const int* in_sizes, int n_in,
                              void* d_out, int out_size)
{
    const float*         inp   = (const float*)d_in[0];
    const unsigned char* mask  = (const unsigned char*)d_in[1];
    const float*         w_qkv = (const float*)d_in[2];
    const float*         b_qkv = (const float*)d_in[3];
    const float*         w_out = (const float*)d_in[4];
    const float*         b_out = (const float*)d_in[5];
    float*               out   = (float*)d_out;

    float *qkv_p, *att_p, *xr_p, *wqT_p, *woT_p;
    cudaGetSymbolAddress((void**)&qkv_p, g_qkv);
    cudaGetSymbolAddress((void**)&att_p, g_att);
    cudaGetSymbolAddress((void**)&xr_p,  g_xr);
    cudaGetSymbolAddress((void**)&wqT_p, g_wqT);
    cudaGetSymbolAddress((void**)&woT_p, g_woT);

    cudaFuncSetAttribute(attn_mma,
                         cudaFuncAttributeMaxDynamicSharedMemorySize, ATTN_SMEM);
    cudaFuncSetAttribute(tgemm_ldsm,
                         cudaFuncAttributeMaxDynamicSharedMemorySize, TG_SMEM);

    len_kernel<<<BB, 256>>>(mask);
    cvt_pre<<<512, 256>>>((const float4*)inp, (float4*)xr_p,
                          (BB * TT * HH) / 4);
    transpose_w<<<dim3(H3 / 32, HH / 32), dim3(32, 8)>>>(w_qkv, wqT_p, HH, H3);
    transpose_w<<<dim3(HH / 32, HH / 32), dim3(32, 8)>>>(w_out, woT_p, HH, HH);

    tgemm_ldsm<<<dim3(H3 / 128, (BB * TT) / 128), 256, TG_SMEM>>>(
        xr_p, wqT_p, b_qkv, qkv_p, BB * TT, H3, HH);
    attn_mma<<<dim3(TT / 64, BB * NH), 256, ATTN_SMEM>>>(qkv_p, att_p);
    tgemm_ldsm<<<dim3(HH / 128, (BB * TT) / 128), 256, TG_SMEM>>>(
        att_p, woT_p, b_out, out, BB * TT, HH, HH);
}